// round 2
// baseline (speedup 1.0000x reference)
#include <cuda_runtime.h>
#include <cuda_bf16.h>
#include <stdint.h>

#define HD 1024
#define TT 4096
#define NB0 32
#define NB12 57
#define GRIDN (NB0 + 2*NB12)   /* 146 persistent blocks */
#define NTHR 256
#define NITER (TT + 2)

#define K0 1024
#define K12 2048
#define WSMEM_BYTES 212992     /* 52 rows * 4096B == 104 rows * 2048B */
#define WSMEM_U4 (WSMEM_BYTES/16)

#define OFF1 (NB0*128*1024)            /* 4194304  */
#define SEG12 (NB12*72*2048)           /* 8404992  */
#define OFF2 (OFF1 + SEG12)
#define WTOT (OFF1 + 2*SEG12)          /* 21004288 */

// ---------------- static device storage (no allocations) ----------------
__device__ __align__(16) __nv_bfloat16 g_wblob[WTOT];           // ~42 MB
__device__ float g_bias[NB0*128 + 2*NB12*72];                   // 12304
__device__ float g_wih0[NB0*128*2];                             // 8192
__device__ __align__(16) float g_hbuf[2*3*HD];                  // double-buffered h
__device__ float g_ys[(size_t)TT*HD];                           // 16 MB: top-layer h per t
__device__ volatile int g_epoch;
__device__ int g_count;

__device__ __forceinline__ float bflo(unsigned u){ return __uint_as_float(u << 16); }
__device__ __forceinline__ float bfhi(unsigned u){ return __uint_as_float(u & 0xffff0000u); }
__device__ __forceinline__ float sigmoidf_(float x){ return 1.0f/(1.0f + __expf(-x)); }

// ---------------- prep: repack weights into per-block bf16 blobs ----------------
__global__ void prep_w(const float* __restrict__ Whh0,
                       const float* __restrict__ Wih12,
                       const float* __restrict__ Whh12)
{
    for (long long i = (long long)blockIdx.x*blockDim.x + threadIdx.x; i < (long long)WTOT;
         i += (long long)gridDim.x*blockDim.x) {
        float val;
        if (i < (long long)OFF1) {
            int b   = (int)(i >> 17);          // /(128*1024)
            int rem = (int)(i & 131071);
            int r   = rem >> 10;
            int col = rem & 1023;
            int grow = (r & 3)*HD + b*32 + (r >> 2);
            val = Whh0[(long long)grow*1024 + col];
        } else {
            int l = (i < (long long)OFF2) ? 0 : 1;
            long long j = i - (l ? (long long)OFF2 : (long long)OFF1);
            int b   = (int)(j / 147456);       // 72*2048
            int rem = (int)(j % 147456);
            int r   = rem >> 11;
            int col = rem & 2047;
            int ih  = r >> 2;
            int CHb = (b == NB12-1) ? 16 : 18;
            if (ih >= CHb) val = 0.0f;
            else {
                int grow = (r & 3)*HD + b*18 + ih;
                if (col < 1024) val = Wih12[(long long)l*4194304 + (long long)grow*1024 + col];
                else            val = Whh12[(long long)l*4194304 + (long long)grow*1024 + (col-1024)];
            }
        }
        g_wblob[i] = __float2bfloat16(val);
    }
}

// ---------------- prep: biases, W_ih0 pack, state/barrier reset ----------------
__global__ void prep_small(const float* __restrict__ Wih0,
                           const float* __restrict__ bih0, const float* __restrict__ bhh0,
                           const float* __restrict__ bih12, const float* __restrict__ bhh12)
{
    int i = blockIdx.x*blockDim.x + threadIdx.x;
    int n = blockDim.x*gridDim.x;
    for (int k = i; k < 2*3*HD; k += n) g_hbuf[k] = 0.0f;
    for (int k = i; k < NB0*128 + 2*NB12*72; k += n) {
        float v;
        if (k < NB0*128) {
            int b = k >> 7, r = k & 127;
            int grow = (r & 3)*HD + b*32 + (r >> 2);
            v = bih0[grow] + bhh0[grow];
        } else {
            int j  = k - NB0*128;
            int l  = j / (NB12*72);
            int jj = j - l*(NB12*72);
            int b  = jj / 72, r = jj % 72;
            int ih = r >> 2;
            int CHb = (b == NB12-1) ? 16 : 18;
            if (ih >= CHb) v = 0.0f;
            else {
                int grow = (r & 3)*HD + b*18 + ih;
                v = bih12[l*4096 + grow] + bhh12[l*4096 + grow];
            }
        }
        g_bias[k] = v;
    }
    for (int k = i; k < NB0*128*2; k += n) {
        int b = k >> 8;
        int r = (k >> 1) & 127;
        int c = k & 1;
        int grow = (r & 3)*HD + b*32 + (r >> 2);
        g_wih0[k] = Wih0[grow*2 + c];
    }
    if (i == 0) { g_epoch = 0; g_count = 0; }
}

// ---------------- row dot-product engine ----------------
template<int NJ, bool IS_L0>
__device__ __forceinline__ void compute_rows(
    const uint4* __restrict__ sw, const uint4* __restrict__ gw,
    int R, int smemRows, int rowU4,
    const float* __restrict__ vin, float* __restrict__ gates,
    const float* __restrict__ bias, const float* __restrict__ wih0,
    float x0, float x1, int lane, int wid)
{
    // register-cache this lane's slice of the input vector (reused across rows)
    float v[NJ*8];
#pragma unroll
    for (int j = 0; j < NJ; j++) {
        const float* p = vin + (j*32 + lane)*8;
        float4 a = *(const float4*)(p);
        float4 b = *(const float4*)(p + 4);
        v[j*8+0]=a.x; v[j*8+1]=a.y; v[j*8+2]=a.z; v[j*8+3]=a.w;
        v[j*8+4]=b.x; v[j*8+5]=b.y; v[j*8+6]=b.z; v[j*8+7]=b.w;
    }
    int r = wid;
    // smem-cached rows
    for (; r < smemRows; r += 8) {
        const uint4* wr = sw + r*rowU4 + lane;
        float a0=0.f, a1=0.f, a2=0.f, a3=0.f;
#pragma unroll
        for (int j = 0; j < NJ; j++) {
            uint4 w = wr[j*32];
            a0 += bflo(w.x)*v[j*8+0]; a1 += bfhi(w.x)*v[j*8+1];
            a2 += bflo(w.y)*v[j*8+2]; a3 += bfhi(w.y)*v[j*8+3];
            a0 += bflo(w.z)*v[j*8+4]; a1 += bfhi(w.z)*v[j*8+5];
            a2 += bflo(w.w)*v[j*8+6]; a3 += bfhi(w.w)*v[j*8+7];
        }
        float s = (a0+a1) + (a2+a3);
#pragma unroll
        for (int o = 16; o; o >>= 1) s += __shfl_xor_sync(0xffffffffu, s, o);
        if (lane == 0) {
            s += bias[r];
            if (IS_L0) s += wih0[2*r]*x0 + wih0[2*r+1]*x1;
            gates[r] = s;
        }
    }
    // L2-streamed rows
    for (; r < R; r += 8) {
        const uint4* wr = gw + r*rowU4 + lane;
        float a0=0.f, a1=0.f, a2=0.f, a3=0.f;
#pragma unroll
        for (int j = 0; j < NJ; j++) {
            uint4 w = __ldg(wr + j*32);
            a0 += bflo(w.x)*v[j*8+0]; a1 += bfhi(w.x)*v[j*8+1];
            a2 += bflo(w.y)*v[j*8+2]; a3 += bfhi(w.y)*v[j*8+3];
            a0 += bflo(w.z)*v[j*8+4]; a1 += bfhi(w.z)*v[j*8+5];
            a2 += bflo(w.w)*v[j*8+6]; a3 += bfhi(w.w)*v[j*8+7];
        }
        float s = (a0+a1) + (a2+a3);
#pragma unroll
        for (int o = 16; o; o >>= 1) s += __shfl_xor_sync(0xffffffffu, s, o);
        if (lane == 0) {
            s += bias[r];
            if (IS_L0) s += wih0[2*r]*x0 + wih0[2*r+1]*x1;
            gates[r] = s;
        }
    }
}

// ---------------- persistent pipelined LSTM kernel ----------------
__global__ void __launch_bounds__(NTHR, 1) lstm_main(const float* __restrict__ x)
{
    extern __shared__ unsigned char s_raw[];
    uint4* s_w = (uint4*)s_raw;
    __shared__ float s_vin[2048];
    __shared__ float s_gates[128];
    __shared__ float s_bias[128];
    __shared__ float s_wih0[256];
    __shared__ float s_c[32];

    const int tid = threadIdx.x, lane = tid & 31, wid = tid >> 5;
    const int b = blockIdx.x;
    int layer, idx;
    if (b < NB0)            { layer = 0; idx = b; }
    else if (b < NB0+NB12)  { layer = 1; idx = b - NB0; }
    else                    { layer = 2; idx = b - (NB0+NB12); }

    int CH, hbase, R, rowU4, smemRows;
    long long woff; int boff;
    if (layer == 0) {
        CH = 32; hbase = idx*32; R = 128; rowU4 = K0/8; smemRows = 104;
        woff = (long long)idx*128*1024; boff = idx*128;
    } else {
        CH = (idx == NB12-1) ? 16 : 18; hbase = idx*18; R = 4*CH;
        rowU4 = K12/8; smemRows = 52;
        woff = (long long)OFF1 + (long long)(layer-1)*SEG12 + (long long)idx*72*2048;
        boff = NB0*128 + (layer-1)*NB12*72 + idx*72;
    }
    const uint4* gw = (const uint4*)(g_wblob + woff);

    // one-time: stage first smemRows rows of the weight slice into shared
    for (int i = tid; i < WSMEM_U4; i += NTHR) s_w[i] = gw[i];
    if (tid < R) s_bias[tid] = g_bias[boff + tid];
    if (layer == 0 && tid < 256) s_wih0[tid] = g_wih0[idx*256 + tid];
    if (tid < CH) s_c[tid] = 0.0f;
    __syncthreads();

    for (int iter = 0; iter < NITER; ++iter) {
        const int t = iter - layer;
        if (t >= 0 && t < TT) {
            const int pr = (iter - 1) & 1;
            const float* hb = g_hbuf + pr*(3*HD);
            if (layer == 0) {
                ((float4*)s_vin)[tid] = ((const float4*)hb)[tid];            // own h (1024)
            } else {
                ((float4*)s_vin)[tid]       = ((const float4*)(hb + (layer-1)*HD))[tid]; // input h
                ((float4*)s_vin)[256 + tid] = ((const float4*)(hb +  layer   *HD))[tid]; // own h
            }
            float x0 = 0.f, x1 = 0.f;
            if (layer == 0) { x0 = x[2*t]; x1 = x[2*t + 1]; }
            __syncthreads();

            if (layer == 0)
                compute_rows<4, true >(s_w, gw, R, smemRows, rowU4, s_vin, s_gates, s_bias, s_wih0, x0, x1, lane, wid);
            else
                compute_rows<8, false>(s_w, gw, R, smemRows, rowU4, s_vin, s_gates, s_bias, s_wih0, 0.f, 0.f, lane, wid);

            __syncthreads();
            if (tid < CH) {
                float gi = s_gates[tid*4+0];
                float gf = s_gates[tid*4+1];
                float gg = s_gates[tid*4+2];
                float go = s_gates[tid*4+3];
                float ig = sigmoidf_(gi);
                float fg = sigmoidf_(gf);
                float gv = tanhf(gg);
                float og = sigmoidf_(go);
                float c  = fg*s_c[tid] + ig*gv;
                s_c[tid] = c;
                float h  = og*tanhf(c);
                g_hbuf[(iter & 1)*(3*HD) + layer*HD + hbase + tid] = h;
                if (layer == 2) g_ys[(size_t)t*HD + hbase + tid] = h;
            }
        }
        // ------- grid barrier (sense-free epoch counter) -------
        __syncthreads();
        if (tid == 0) {
            __threadfence();
            int old = atomicAdd(&g_count, 1);
            if (old == GRIDN - 1) {
                atomicExch(&g_count, 0);
                __threadfence();
                g_epoch = iter + 1;
            } else {
                while (g_epoch <= iter) { }
                __threadfence();
            }
        }
        __syncthreads();
    }
}

// ---------------- output head ----------------
__global__ void finalize_k(const float* __restrict__ Wres, const float* __restrict__ bres,
                           float* __restrict__ out)
{
    __shared__ float sred[4];
    const int t = blockIdx.x;
    const int tid = threadIdx.x;
    float s = 0.0f;
    for (int k = tid; k < HD; k += 128) s += g_ys[(size_t)t*HD + k] * Wres[k];
#pragma unroll
    for (int o = 16; o; o >>= 1) s += __shfl_xor_sync(0xffffffffu, s, o);
    if ((tid & 31) == 0) sred[tid >> 5] = s;
    __syncthreads();
    if (tid == 0) {
        float tot = sred[0] + sred[1] + sred[2] + sred[3];
        out[t] = 1.0f/(1.0f + __expf(-(tot + bres[0])));
    }
}

// ---------------- launch ----------------
extern "C" void kernel_launch(void* const* d_in, const int* in_sizes, int n_in,
                              void* d_out, int out_size)
{
    const float* x     = (const float*)d_in[0];
    const float* Wih0  = (const float*)d_in[1];
    const float* Whh0  = (const float*)d_in[2];
    const float* bih0  = (const float*)d_in[3];
    const float* bhh0  = (const float*)d_in[4];
    const float* Wih12 = (const float*)d_in[5];
    const float* Whh12 = (const float*)d_in[6];
    const float* bih12 = (const float*)d_in[7];
    const float* bhh12 = (const float*)d_in[8];
    const float* Wres  = (const float*)d_in[9];
    const float* bres  = (const float*)d_in[10];
    float* out = (float*)d_out;

    cudaFuncSetAttribute(lstm_main, cudaFuncAttributeMaxDynamicSharedMemorySize, WSMEM_BYTES);

    prep_small<<<26, 256>>>(Wih0, bih0, bhh0, bih12, bhh12);
    prep_w<<<2048, 256>>>(Whh0, Wih12, Whh12);
    lstm_main<<<GRIDN, NTHR, WSMEM_BYTES>>>(x);
    finalize_k<<<TT, 128>>>(Wres, bres, out);
}

// round 3
// speedup vs baseline: 1.7772x; 1.7772x over previous
#include <cuda_runtime.h>
#include <cuda_bf16.h>
#include <stdint.h>

#define HD 1024
#define TT 4096
#define NB0 32
#define NB12 57
#define GRIDN (NB0 + 2*NB12)   /* 146 persistent blocks */
#define NTHR 384
#define NW 12                  /* warps per block */

#define OFF1 (NB0*128*1024)            /* 4194304  */
#define SEG12 (NB12*72*2048)           /* 8404992  */
#define OFF2 (OFF1 + SEG12)
#define WTOT (OFF1 + 2*SEG12)          /* 21004288 */

#define DSMEM_BYTES 212992             /* 104 rows * 2048B == 13312 uint4 */

// ---------------- static device storage (no allocations) ----------------
__device__ __align__(16) __nv_bfloat16 g_wblob[WTOT];            // ~42 MB bf16 weights
__device__ float g_bias[NB0*128 + 2*NB12*72];                    // fused biases
__device__ float g_wih0[NB0*128*2];                              // layer0 W_ih (2 cols)
__device__ __align__(16) __nv_bfloat16 g_hall[(size_t)(TT+1)*3*HD]; // h history, write-once
__device__ int g_cnt[3*TT];                                      // per-(layer,t) completion

__device__ __forceinline__ __nv_bfloat162 u2b(unsigned u) {
    return *reinterpret_cast<const __nv_bfloat162*>(&u);
}
__device__ __forceinline__ float sigm(float v)  { return __fdividef(1.0f, 1.0f + __expf(-v)); }
__device__ __forceinline__ float ftanh(float v) {
    v = fminf(fmaxf(v, -30.0f), 30.0f);
    float e = __expf(2.0f*v);
    return __fdividef(e - 1.0f, e + 1.0f);
}

// ---------------- prep: repack weights into per-block bf16 blobs ----------------
__global__ void prep_w(const float* __restrict__ Whh0,
                       const float* __restrict__ Wih12,
                       const float* __restrict__ Whh12)
{
    for (long long i = (long long)blockIdx.x*blockDim.x + threadIdx.x; i < (long long)WTOT;
         i += (long long)gridDim.x*blockDim.x) {
        float val;
        if (i < (long long)OFF1) {
            int b   = (int)(i >> 17);
            int rem = (int)(i & 131071);
            int r   = rem >> 10;
            int col = rem & 1023;
            int grow = (r & 3)*HD + b*32 + (r >> 2);
            val = Whh0[(long long)grow*1024 + col];
        } else {
            int l = (i < (long long)OFF2) ? 0 : 1;
            long long j = i - (l ? (long long)OFF2 : (long long)OFF1);
            int b   = (int)(j / 147456);
            int rem = (int)(j % 147456);
            int r   = rem >> 11;
            int col = rem & 2047;
            int ih  = r >> 2;
            int CHb = (b == NB12-1) ? 16 : 18;
            if (ih >= CHb) val = 0.0f;
            else {
                int grow = (r & 3)*HD + b*18 + ih;
                if (col < 1024) val = Wih12[(long long)l*4194304 + (long long)grow*1024 + col];
                else            val = Whh12[(long long)l*4194304 + (long long)grow*1024 + (col-1024)];
            }
        }
        g_wblob[i] = __float2bfloat16(val);
    }
}

// ---------------- prep: biases, W_ih0, state/flag reset ----------------
__global__ void prep_small(const float* __restrict__ Wih0,
                           const float* __restrict__ bih0, const float* __restrict__ bhh0,
                           const float* __restrict__ bih12, const float* __restrict__ bhh12)
{
    int i = blockIdx.x*blockDim.x + threadIdx.x;
    int n = blockDim.x*gridDim.x;
    for (int k = i; k < 3*TT; k += n) g_cnt[k] = 0;
    for (int k = i; k < 3*HD; k += n) g_hall[k] = __float2bfloat16(0.0f);  // slot 0 = h_{-1}=0
    for (int k = i; k < NB0*128 + 2*NB12*72; k += n) {
        float v;
        if (k < NB0*128) {
            int b = k >> 7, r = k & 127;
            int grow = (r & 3)*HD + b*32 + (r >> 2);
            v = bih0[grow] + bhh0[grow];
        } else {
            int j  = k - NB0*128;
            int l  = j / (NB12*72);
            int jj = j - l*(NB12*72);
            int b  = jj / 72, r = jj % 72;
            int ih = r >> 2;
            int CHb = (b == NB12-1) ? 16 : 18;
            if (ih >= CHb) v = 0.0f;
            else {
                int grow = (r & 3)*HD + b*18 + ih;
                v = bih12[l*4096 + grow] + bhh12[l*4096 + grow];
            }
        }
        g_bias[k] = v;
    }
    for (int k = i; k < NB0*128*2; k += n) {
        int b = k >> 8;
        int r = (k >> 1) & 127;
        int c = k & 1;
        int grow = (r & 3)*HD + b*32 + (r >> 2);
        g_wih0[k] = Wih0[grow*2 + c];
    }
}

// ---------------- dot-product primitives (bf16x2 HFMA2) ----------------
template<int NJ>
__device__ __forceinline__ float dot_rr(const uint4 (&w)[NJ], const uint4 (&v)[NJ])
{
    __nv_bfloat162 z = __floats2bfloat162_rn(0.0f, 0.0f);
    __nv_bfloat162 a0 = z, a1 = z, a2 = z, a3 = z;
#pragma unroll
    for (int j = 0; j < NJ; j++) {
        a0 = __hfma2(u2b(w[j].x), u2b(v[j].x), a0);
        a1 = __hfma2(u2b(w[j].y), u2b(v[j].y), a1);
        a2 = __hfma2(u2b(w[j].z), u2b(v[j].z), a2);
        a3 = __hfma2(u2b(w[j].w), u2b(v[j].w), a3);
    }
    __nv_bfloat162 s2 = __hadd2(__hadd2(a0, a1), __hadd2(a2, a3));
    float2 f = __bfloat1622float2(s2);
    return f.x + f.y;
}

template<int NJ>
__device__ __forceinline__ float dot_sm(const uint4* __restrict__ wbase, int lane, const uint4 (&v)[NJ])
{
    __nv_bfloat162 z = __floats2bfloat162_rn(0.0f, 0.0f);
    __nv_bfloat162 a0 = z, a1 = z, a2 = z, a3 = z;
#pragma unroll
    for (int j = 0; j < NJ; j++) {
        uint4 w = wbase[j*32 + lane];
        a0 = __hfma2(u2b(w.x), u2b(v[j].x), a0);
        a1 = __hfma2(u2b(w.y), u2b(v[j].y), a1);
        a2 = __hfma2(u2b(w.z), u2b(v[j].z), a2);
        a3 = __hfma2(u2b(w.w), u2b(v[j].w), a3);
    }
    __nv_bfloat162 s2 = __hadd2(__hadd2(a0, a1), __hadd2(a2, a3));
    float2 f = __bfloat1622float2(s2);
    return f.x + f.y;
}

__device__ __forceinline__ void finish_row(float s, int r, bool is0, float x0, float x1,
                                           const float* __restrict__ s_bias,
                                           const float* __restrict__ s_wih0,
                                           float* __restrict__ s_gates, int lane)
{
#pragma unroll
    for (int o = 16; o; o >>= 1) s += __shfl_xor_sync(0xffffffffu, s, o);
    if (lane == 0) {
        s += s_bias[r];
        if (is0) s += s_wih0[2*r]*x0 + s_wih0[2*r+1]*x1;
        s_gates[r] = s;
    }
}

// ---------------- persistent dataflow LSTM kernel ----------------
__global__ void __launch_bounds__(NTHR, 1) lstm_main(const float* __restrict__ x)
{
    extern __shared__ uint4 s_w4[];     // cached weight rows (rows >= 24)
    __shared__ uint4 s_v4[256];         // staged input vector (up to 2048 bf16)
    __shared__ float s_gates[128];
    __shared__ float s_bias[128];
    __shared__ float s_wih0[256];
    __shared__ float s_c[32];

    const int tid = threadIdx.x, lane = tid & 31, wid = tid >> 5;
    const int b = blockIdx.x;
    int layer, idx;
    if (b < NB0)             { layer = 0; idx = b; }
    else if (b < NB0+NB12)   { layer = 1; idx = b - NB0; }
    else                     { layer = 2; idx = b - (NB0+NB12); }

    int CH, hbase, R, rowU4, NBown, NBlow, boff;
    long long woff;
    if (layer == 0) {
        CH = 32; hbase = idx*32; R = 128; rowU4 = 128;
        woff = (long long)idx*131072; boff = idx*128;
        NBown = NB0; NBlow = 0;
    } else {
        CH = (idx == NB12-1) ? 16 : 18; hbase = idx*18; R = 4*CH; rowU4 = 256;
        woff = (long long)OFF1 + (long long)(layer-1)*SEG12 + (long long)idx*147456;
        boff = NB0*128 + (layer-1)*(NB12*72) + idx*72;
        NBown = NB12; NBlow = (layer == 1) ? NB0 : NB12;
    }
    const uint4* gw = (const uint4*)(g_wblob + woff);

    // one-time: stage rows [24, R) into smem
    const int smU4 = (R - 2*NW) * rowU4;
    for (int i2 = tid; i2 < smU4; i2 += NTHR) s_w4[i2] = gw[2*NW*rowU4 + i2];
    if (tid < R) s_bias[tid] = g_bias[boff + tid];
    if (layer == 0 && tid < 256) s_wih0[tid] = g_wih0[idx*256 + tid];
    if (tid < 32) s_c[tid] = 0.0f;

    // one-time: register-cache rows wid and wid+NW
    uint4 wr0[8], wr1[8];
    if (layer == 0) {
#pragma unroll
        for (int j = 0; j < 4; j++) {
            wr0[j] = gw[(long long)wid*128       + j*32 + lane];
            wr1[j] = gw[(long long)(wid+NW)*128  + j*32 + lane];
        }
    } else {
#pragma unroll
        for (int j = 0; j < 8; j++) {
            wr0[j] = gw[(long long)wid*256       + j*32 + lane];
            wr1[j] = gw[(long long)(wid+NW)*256  + j*32 + lane];
        }
    }
    __syncthreads();

    for (int t = 0; t < TT; ++t) {
        // ---- wait on dataflow flags ----
        if (tid == 0 && t > 0) {
            volatile int* f = &g_cnt[layer*TT + (t-1)];
            while (*f < NBown) { }
            __threadfence();
        }
        if (tid == 32 && layer > 0) {
            volatile int* f = &g_cnt[(layer-1)*TT + t];
            while (*f < NBlow) { }
            __threadfence();
        }
        __syncthreads();

        // ---- stage input vector into smem ----
        if (layer == 0) {
            if (tid < 128)
                s_v4[tid] = *(const uint4*)(g_hall + (size_t)t*3072 + (size_t)tid*8);
        } else {
            if (tid < 256) {
                size_t eoff = (tid < 128)
                    ? ((size_t)(t+1)*3072 + (size_t)(layer-1)*1024 + (size_t)tid*8)
                    : ((size_t)t*3072     + (size_t)layer*1024     + (size_t)(tid-128)*8);
                s_v4[tid] = *(const uint4*)(g_hall + eoff);
            }
        }
        __syncthreads();

        float x0 = 0.0f, x1 = 0.0f;
        if (layer == 0) { x0 = __ldg(&x[2*t]); x1 = __ldg(&x[2*t + 1]); }

        // ---- matvec rows ----
        if (layer == 0) {
            uint4 vv[4];
#pragma unroll
            for (int j = 0; j < 4; j++) vv[j] = s_v4[j*32 + lane];
            float s;
            s = dot_rr<4>(*(const uint4(*)[4])&wr0[0], vv);
            finish_row(s, wid, true, x0, x1, s_bias, s_wih0, s_gates, lane);
            s = dot_rr<4>(*(const uint4(*)[4])&wr1[0], vv);
            finish_row(s, wid+NW, true, x0, x1, s_bias, s_wih0, s_gates, lane);
            for (int r = wid + 2*NW; r < 128; r += NW) {
                s = dot_sm<4>(s_w4 + (r-2*NW)*128, lane, vv);
                finish_row(s, r, true, x0, x1, s_bias, s_wih0, s_gates, lane);
            }
        } else {
            uint4 vv[8];
#pragma unroll
            for (int j = 0; j < 8; j++) vv[j] = s_v4[j*32 + lane];
            float s;
            s = dot_rr<8>(wr0, vv);
            finish_row(s, wid, false, 0.f, 0.f, s_bias, s_wih0, s_gates, lane);
            s = dot_rr<8>(wr1, vv);
            finish_row(s, wid+NW, false, 0.f, 0.f, s_bias, s_wih0, s_gates, lane);
            for (int r = wid + 2*NW; r < R; r += NW) {
                s = dot_sm<8>(s_w4 + (r-2*NW)*256, lane, vv);
                finish_row(s, r, false, 0.f, 0.f, s_bias, s_wih0, s_gates, lane);
            }
        }
        __syncthreads();

        // ---- pointwise + publish ----
        if (tid < CH) {
            float gi = s_gates[4*tid+0];
            float gf = s_gates[4*tid+1];
            float gg = s_gates[4*tid+2];
            float go = s_gates[4*tid+3];
            float ig = sigm(gi);
            float fg = sigm(gf);
            float gv = ftanh(gg);
            float og = sigm(go);
            float c  = fg*s_c[tid] + ig*gv;
            s_c[tid] = c;
            g_hall[(size_t)(t+1)*3072 + (size_t)layer*1024 + hbase + tid] =
                __float2bfloat16(og*ftanh(c));
            __threadfence();
        }
        __syncthreads();
        if (tid == 0) atomicAdd(&g_cnt[layer*TT + t], 1);
    }
}

// ---------------- output head ----------------
__global__ void finalize_k(const float* __restrict__ Wres, const float* __restrict__ bres,
                           float* __restrict__ out)
{
    __shared__ float sred[4];
    const int t = blockIdx.x;
    const int tid = threadIdx.x;
    const __nv_bfloat16* h = g_hall + (size_t)(t+1)*3072 + 2048;
    float s = 0.0f;
    for (int k = tid; k < HD; k += 128) s += __bfloat162float(h[k]) * Wres[k];
#pragma unroll
    for (int o = 16; o; o >>= 1) s += __shfl_xor_sync(0xffffffffu, s, o);
    if ((tid & 31) == 0) sred[tid >> 5] = s;
    __syncthreads();
    if (tid == 0) {
        float tot = sred[0] + sred[1] + sred[2] + sred[3];
        out[t] = 1.0f/(1.0f + __expf(-(tot + bres[0])));
    }
}

// ---------------- launch ----------------
extern "C" void kernel_launch(void* const* d_in, const int* in_sizes, int n_in,
                              void* d_out, int out_size)
{
    const float* x     = (const float*)d_in[0];
    const float* Wih0  = (const float*)d_in[1];
    const float* Whh0  = (const float*)d_in[2];
    const float* bih0  = (const float*)d_in[3];
    const float* bhh0  = (const float*)d_in[4];
    const float* Wih12 = (const float*)d_in[5];
    const float* Whh12 = (const float*)d_in[6];
    const float* bih12 = (const float*)d_in[7];
    const float* bhh12 = (const float*)d_in[8];
    const float* Wres  = (const float*)d_in[9];
    const float* bres  = (const float*)d_in[10];
    float* out = (float*)d_out;

    cudaFuncSetAttribute(lstm_main, cudaFuncAttributeMaxDynamicSharedMemorySize, DSMEM_BYTES);

    prep_small<<<26, 256>>>(Wih0, bih0, bhh0, bih12, bhh12);
    prep_w<<<2048, 256>>>(Whh0, Wih12, Whh12);
    lstm_main<<<GRIDN, NTHR, DSMEM_BYTES>>>(x);
    finalize_k<<<TT, 128>>>(Wres, bres, out);
}